// round 8
// baseline (speedup 1.0000x reference)
#include <cuda_runtime.h>
#include <mma.h>
#include <cstdint>

using namespace nvcuda;

#define T_  512
#define B_  64
#define H_  1024
#define G_  4096
#define BH  (B_*H_)
#define TBH ((size_t)T_*B_*H_)
#define NCTA 128

// ---------------- device scratch (no allocations allowed) ----------------
__device__ float    g_xin[(size_t)T_*B_*G_];     // input projection (per layer, reused)
__device__ float    g_seq0[(size_t)T_*B_*H_];    // layer-0 output seq (stored tf32-rounded)
__device__ float    g_xr[(size_t)T_*B_*H_];      // tf32-rounded x
__device__ float    g_wr[(size_t)2*G_*H_];       // tf32-rounded w_ih (both layers)
__device__ float    g_h[2*BH];                   // double-buffered h state
__device__ unsigned g_flag[NCTA];                // per-CTA step flags

__device__ __forceinline__ uint32_t smem_u32(const void* p) {
    uint32_t a;
    asm("{ .reg .u64 t; cvta.to.shared.u64 t, %1; cvt.u32.u64 %0, t; }" : "=r"(a) : "l"(p));
    return a;
}
#define CP_ASYNC16(dst_u32, src_ptr) \
    asm volatile("cp.async.cg.shared.global [%0], [%1], 16;" :: "r"(dst_u32), "l"(src_ptr))
#define CP_COMMIT() asm volatile("cp.async.commit_group;" ::: "memory")
#define CP_WAIT0()  asm volatile("cp.async.wait_group 0;" ::: "memory")

// ---------------- init: zero h buffers + flags ----------------
__global__ void init_kernel() {
    int i = blockIdx.x * blockDim.x + threadIdx.x;   // 32768 threads
    #pragma unroll
    for (int k = 0; k < 4; k++) g_h[i + k * 32768] = 0.0f;
    if (i < NCTA) g_flag[i] = 0u;
}

// ---------------- pre-round x and w_ih to tf32 (RN) ----------------
#define XF4 ((size_t)T_*B_*H_/4)      // 8,388,608 float4
#define WF4 ((size_t)2*G_*H_/4)       // 2,097,152 float4
__global__ void round_all(const float* __restrict__ x, const float* __restrict__ wih) {
    const size_t stride = (size_t)gridDim.x * blockDim.x;
    for (size_t i = (size_t)blockIdx.x * blockDim.x + threadIdx.x; i < XF4 + WF4; i += stride) {
        float4 v; float4* dst;
        if (i < XF4) {
            v = reinterpret_cast<const float4*>(x)[i];
            dst = reinterpret_cast<float4*>(g_xr) + i;
        } else {
            v = reinterpret_cast<const float4*>(wih)[i - XF4];
            dst = reinterpret_cast<float4*>(g_wr) + (i - XF4);
        }
        v.x = wmma::__float_to_tf32(v.x); v.y = wmma::__float_to_tf32(v.y);
        v.z = wmma::__float_to_tf32(v.z); v.w = wmma::__float_to_tf32(v.w);
        *dst = v;
    }
}

// ============ Stage 1: xin[32768,4096] = A[32768,1024] @ W[4096,1024]^T ============
// Tile 128x128, kc=32, cp.async double-buffered. 8 warps = 2(M) x 4(N), warp 64x32.
#define GX_BUF  (128*40)                     // floats per A (or B) buffer
#define GX_SMEM (4*GX_BUF*4)                 // 81920 bytes
__global__ __launch_bounds__(256) void gemm_xin(int layer) {
    extern __shared__ float smf[];
    float* As = smf;                          // [2][128*40]
    float* Bs = smf + 2*GX_BUF;               // [2][128*40]

    const float* A = (layer == 0) ? g_xr : g_seq0;
    const float* W = g_wr + (size_t)layer * (size_t)G_ * H_;

    const int tid  = threadIdx.x;
    const int warp = tid >> 5;
    const int wm   = warp >> 2;
    const int wn   = warp & 3;
    const size_t m0 = (size_t)blockIdx.y * 128;
    const int    n0 = blockIdx.x * 128;

    const int r = tid >> 3, c = (tid & 7) << 2;   // this thread's (row, col4) pattern
    const uint32_t sa = smem_u32(As), sb = smem_u32(Bs);

    wmma::fragment<wmma::accumulator,16,16,8,float> acc[4][2];
    #pragma unroll
    for (int mi = 0; mi < 4; mi++)
        #pragma unroll
        for (int ni = 0; ni < 2; ni++)
            wmma::fill_fragment(acc[mi][ni], 0.0f);

    // preload kc=0 into buffer 0
    #pragma unroll
    for (int i = 0; i < 4; i++) {
        int rr = r + i*32;
        CP_ASYNC16(sa + (uint32_t)(rr*40 + c)*4, &A[(m0 + rr)*1024 + c]);
        CP_ASYNC16(sb + (uint32_t)(rr*40 + c)*4, &W[(size_t)(n0 + rr)*1024 + c]);
    }
    CP_COMMIT();

    for (int it = 0; it < 32; ++it) {
        const int buf = it & 1;
        CP_WAIT0();
        __syncthreads();
        if (it < 31) {
            const int kc = (it + 1) * 32;
            const uint32_t da = sa + (uint32_t)((buf^1)*GX_BUF)*4;
            const uint32_t db = sb + (uint32_t)((buf^1)*GX_BUF)*4;
            #pragma unroll
            for (int i = 0; i < 4; i++) {
                int rr = r + i*32;
                CP_ASYNC16(da + (uint32_t)(rr*40 + c)*4, &A[(m0 + rr)*1024 + kc + c]);
                CP_ASYNC16(db + (uint32_t)(rr*40 + c)*4, &W[(size_t)(n0 + rr)*1024 + kc + c]);
            }
            CP_COMMIT();
        }
        const float* Ab = As + buf*GX_BUF;
        const float* Bb = Bs + buf*GX_BUF;
        #pragma unroll
        for (int k8 = 0; k8 < 4; k8++) {
            wmma::fragment<wmma::matrix_a,16,16,8,wmma::precision::tf32,wmma::row_major> af[4];
            wmma::fragment<wmma::matrix_b,16,16,8,wmma::precision::tf32,wmma::col_major> bf[2];
            #pragma unroll
            for (int mi = 0; mi < 4; mi++)
                wmma::load_matrix_sync(af[mi], &Ab[(wm*64 + mi*16)*40 + k8*8], 40);
            #pragma unroll
            for (int ni = 0; ni < 2; ni++)
                wmma::load_matrix_sync(bf[ni], &Bb[(wn*32 + ni*16)*40 + k8*8], 40);
            #pragma unroll
            for (int mi = 0; mi < 4; mi++)
                #pragma unroll
                for (int ni = 0; ni < 2; ni++)
                    wmma::mma_sync(acc[mi][ni], af[mi], bf[ni], acc[mi][ni]);
        }
    }
    #pragma unroll
    for (int mi = 0; mi < 4; mi++)
        #pragma unroll
        for (int ni = 0; ni < 2; ni++)
            wmma::store_matrix_sync(
                &g_xin[(m0 + wm*64 + mi*16)*(size_t)G_ + n0 + wn*32 + ni*16],
                acc[mi][ni], G_, wmma::mem_row_major);
}

// ============ Stage 2: persistent recurrence, 128 co-resident CTAs ============
//  Ws 32x1028 @0 | Hs 64x132 @32896 | Ps 8x32x36 @41344 | Cs 512 @50560 | Bsum 32 @51072
#define OFF_HS  32896
#define OFF_PS  41344
#define OFF_CS  50560
#define OFF_BS  51072
#define SMEM_FLOATS 51104
#define SMEM_BYTES  (SMEM_FLOATS*4)

__global__ __launch_bounds__(256) void lstm_rec(const float* __restrict__ whh,
                                                const float* __restrict__ bih,
                                                const float* __restrict__ bhh,
                                                float* __restrict__ out,
                                                int layer) {
    extern __shared__ float smf[];
    float* Ws   = smf;
    float* Hs   = smf + OFF_HS;
    float* Ps   = smf + OFF_PS;
    float* Cs   = smf + OFF_CS;
    float* Bsum = smf + OFF_BS;

    const int tid  = threadIdx.x;
    const int warp = tid >> 5;
    const int lane = tid & 31;
    const int wm   = warp & 1;
    const int wk   = warp >> 1;
    const int j0   = blockIdx.x * 8;

    const float* whh_l = whh + (size_t)layer * (size_t)G_ * H_;
    const float* bih_l = bih + (size_t)layer * G_;
    const float* bhh_l = bhh + (size_t)layer * G_;
    float* seq_out = (layer == 0) ? g_seq0 : out;
    float* hn_out  = out + TBH + (size_t)layer * BH;
    float* cn_out  = out + TBH + 2*(size_t)BH + (size_t)layer * BH;

    #pragma unroll 4
    for (int i = 0; i < 32; i++) {
        int idx = i*256 + tid;
        int rr = idx >> 8;
        int cc = (idx & 255) << 2;
        int grow = (rr >> 3) * H_ + j0 + (rr & 7);
        float4 v = *reinterpret_cast<const float4*>(&whh_l[(size_t)grow * H_ + cc]);
        v.x = wmma::__float_to_tf32(v.x); v.y = wmma::__float_to_tf32(v.y);
        v.z = wmma::__float_to_tf32(v.z); v.w = wmma::__float_to_tf32(v.w);
        *reinterpret_cast<float4*>(&Ws[rr*1028 + cc]) = v;
    }
    if (tid < 32) {
        int grow = (tid >> 3) * H_ + j0 + (tid & 7);
        Bsum[tid] = bih_l[grow] + bhh_l[grow];
    }
    Cs[tid] = 0.0f; Cs[tid + 256] = 0.0f;
    __syncthreads();

    const int b0 = tid >> 3, jj = tid & 7;
    const int b1 = (tid + 256) >> 3;

    for (int t = 0; t < T_; ++t) {
        const float* hprev = g_h + (size_t)(t & 1) * BH;
        float*       hnext = g_h + (size_t)((t + 1) & 1) * BH;

        float xr[8];
        {
            const float* xb = g_xin + (size_t)t * B_ * G_ + j0 + jj;
            const float* p0 = xb + (size_t)b0 * G_;
            const float* p1 = xb + (size_t)b1 * G_;
            xr[0]=p0[0]; xr[1]=p0[1024]; xr[2]=p0[2048]; xr[3]=p0[3072];
            xr[4]=p1[0]; xr[5]=p1[1024]; xr[6]=p1[2048]; xr[7]=p1[3072];
        }

        wmma::fragment<wmma::accumulator,16,16,8,float> acc[2][2];
        #pragma unroll
        for (int mi = 0; mi < 2; mi++)
            #pragma unroll
            for (int ni = 0; ni < 2; ni++)
                wmma::fill_fragment(acc[mi][ni], 0.0f);

        float4 hreg[8];
        #pragma unroll
        for (int i = 0; i < 8; i++) {
            int idx = i*256 + tid;
            int rr = idx >> 5, cc = (idx & 31) << 2;
            hreg[i] = __ldcg(reinterpret_cast<const float4*>(&hprev[(size_t)rr*H_ + cc]));
        }

        for (int ch = 0; ch < 8; ch++) {
            const int kc = ch * 128;
            __syncthreads();
            #pragma unroll
            for (int i = 0; i < 8; i++) {
                int idx = i*256 + tid;
                int rr = idx >> 5, cc = (idx & 31) << 2;
                float4 v = hreg[i];
                v.x = wmma::__float_to_tf32(v.x); v.y = wmma::__float_to_tf32(v.y);
                v.z = wmma::__float_to_tf32(v.z); v.w = wmma::__float_to_tf32(v.w);
                *reinterpret_cast<float4*>(&Hs[rr*132 + cc]) = v;
            }
            __syncthreads();
            if (ch < 7) {
                #pragma unroll
                for (int i = 0; i < 8; i++) {
                    int idx = i*256 + tid;
                    int rr = idx >> 5, cc = (idx & 31) << 2;
                    hreg[i] = __ldcg(reinterpret_cast<const float4*>(&hprev[(size_t)rr*H_ + kc + 128 + cc]));
                }
            }
            #pragma unroll
            for (int k8 = 0; k8 < 4; k8++) {
                const int koff = wk*32 + k8*8;
                wmma::fragment<wmma::matrix_a,16,16,8,wmma::precision::tf32,wmma::row_major> af[2];
                wmma::fragment<wmma::matrix_b,16,16,8,wmma::precision::tf32,wmma::col_major> bf[2];
                wmma::load_matrix_sync(af[0], &Hs[(wm*32     )*132 + koff], 132);
                wmma::load_matrix_sync(af[1], &Hs[(wm*32 + 16)*132 + koff], 132);
                wmma::load_matrix_sync(bf[0], &Ws[             kc + koff], 1028);
                wmma::load_matrix_sync(bf[1], &Ws[16*1028    + kc + koff], 1028);
                #pragma unroll
                for (int mi = 0; mi < 2; mi++)
                    #pragma unroll
                    for (int ni = 0; ni < 2; ni++)
                        wmma::mma_sync(acc[mi][ni], af[mi], bf[ni], acc[mi][ni]);
            }
        }

        #pragma unroll
        for (int mi = 0; mi < 2; mi++)
            #pragma unroll
            for (int ni = 0; ni < 2; ni++)
                wmma::store_matrix_sync(&Ps[warp*1152 + (mi*16)*36 + ni*16],
                                        acc[mi][ni], 36, wmma::mem_row_major);
        __syncthreads();

        #pragma unroll
        for (int h2 = 0; h2 < 2; h2++) {
            int e  = tid + h2*256;
            int b  = e >> 3;
            int wmb = b >> 5, br = b & 31;
            float s[4];
            #pragma unroll
            for (int g = 0; g < 4; g++) {
                int n = g*8 + jj;
                float a = Ps[(0*2+wmb)*1152 + br*36 + n]
                        + Ps[(1*2+wmb)*1152 + br*36 + n]
                        + Ps[(2*2+wmb)*1152 + br*36 + n]
                        + Ps[(3*2+wmb)*1152 + br*36 + n];
                s[g] = a + xr[h2*4 + g] + Bsum[n];
            }
            float si = 1.0f / (1.0f + __expf(-s[0]));
            float sf = 1.0f / (1.0f + __expf(-s[1]));
            float so = 1.0f / (1.0f + __expf(-s[3]));
            float cv = sf * Cs[e] + si * tanhf(s[2]);
            float hv = so * tanhf(cv);
            Cs[e] = cv;
            hnext[(size_t)b*H_ + j0 + jj] = hv;
            // layer-0 seq feeds layer-1's tf32 GEMM: store it pre-rounded.
            seq_out[((size_t)t * B_ + b) * H_ + j0 + jj] =
                (layer == 0) ? wmma::__float_to_tf32(hv) : hv;
            if (t == T_ - 1) {
                hn_out[(size_t)b*H_ + j0 + jj] = hv;
                cn_out[(size_t)b*H_ + j0 + jj] = cv;
            }
        }
        __syncthreads();

        if (warp == 0) {
            if (lane == 0) {
                __threadfence();
                *reinterpret_cast<volatile unsigned*>(&g_flag[blockIdx.x]) = (unsigned)(t + 1);
            }
            const unsigned tgt = (unsigned)(t + 1);
            for (;;) {
                unsigned m0 = __ldcg(&g_flag[lane]);
                unsigned m1 = __ldcg(&g_flag[lane + 32]);
                unsigned m2 = __ldcg(&g_flag[lane + 64]);
                unsigned m3 = __ldcg(&g_flag[lane + 96]);
                unsigned mn = min(min(m0, m1), min(m2, m3));
                #pragma unroll
                for (int o = 16; o; o >>= 1)
                    mn = min(mn, __shfl_xor_sync(0xffffffffu, mn, o));
                if (mn >= tgt) break;
                __nanosleep(32);
            }
            __threadfence();
        }
        __syncthreads();
    }
}

// ---------------- launch ----------------
extern "C" void kernel_launch(void* const* d_in, const int* in_sizes, int n_in,
                              void* d_out, int out_size) {
    const float* x   = (const float*)d_in[0];
    const float* wih = (const float*)d_in[1];
    const float* whh = (const float*)d_in[2];
    const float* bih = (const float*)d_in[3];
    const float* bhh = (const float*)d_in[4];
    float* out = (float*)d_out;

    cudaFuncSetAttribute(lstm_rec, cudaFuncAttributeMaxDynamicSharedMemorySize, SMEM_BYTES);
    cudaFuncSetAttribute(gemm_xin, cudaFuncAttributeMaxDynamicSharedMemorySize, GX_SMEM);

    init_kernel<<<128, 256>>>();                                  // my #1
    round_all<<<4096, 256>>>(x, wih);                             // my #2
    gemm_xin<<<dim3(32, 256), 256, GX_SMEM>>>(0);                 // my #3
    lstm_rec<<<NCTA, 256, SMEM_BYTES>>>(whh, bih, bhh, out, 0);   // my #4 -> ncu slot 6
    init_kernel<<<128, 256>>>();
    gemm_xin<<<dim3(32, 256), 256, GX_SMEM>>>(1);
    lstm_rec<<<NCTA, 256, SMEM_BYTES>>>(whh, bih, bhh, out, 1);
}

// round 9
// speedup vs baseline: 1.9811x; 1.9811x over previous
#include <cuda_runtime.h>
#include <cuda_fp16.h>
#include <mma.h>
#include <cstdint>

using namespace nvcuda;

#define T_  512
#define B_  64
#define H_  1024
#define G_  4096
#define BH  (B_*H_)
#define TBH ((size_t)T_*B_*H_)
#define NCTA 128

// ---------------- device scratch (no allocations allowed) ----------------
__device__ float    g_xin[(size_t)T_*B_*G_];     // input projection (fp32, per layer)
__device__ __half   g_xh[TBH];                   // x rounded to fp16
__device__ __half   g_wh[(size_t)2*G_*H_];       // w_ih rounded to fp16
__device__ __half   g_s0h[TBH];                  // layer-0 seq (fp16, feeds layer-1 gemm)
__device__ __half   g_h[2*BH];                   // double-buffered h state (fp16)
__device__ unsigned g_flag[NCTA];                // per-CTA step flags

__device__ __forceinline__ uint32_t smem_u32(const void* p) {
    uint32_t a;
    asm("{ .reg .u64 t; cvta.to.shared.u64 t, %1; cvt.u32.u64 %0, t; }" : "=r"(a) : "l"(p));
    return a;
}
#define CP_ASYNC16(dst_u32, src_ptr) \
    asm volatile("cp.async.cg.shared.global [%0], [%1], 16;" :: "r"(dst_u32), "l"(src_ptr))
#define CP_COMMIT() asm volatile("cp.async.commit_group;" ::: "memory")
#define CP_WAIT(n)  asm volatile("cp.async.wait_group %0;" :: "n"(n) : "memory")

// ---------------- init: zero h buffers + flags ----------------
__global__ void init_kernel() {
    int i = blockIdx.x * blockDim.x + threadIdx.x;   // 32768 threads
    float* hz = reinterpret_cast<float*>(g_h);       // 2*BH halves = 65536 floats
    hz[i] = 0.0f; hz[i + 32768] = 0.0f;
    if (i < NCTA) g_flag[i] = 0u;
}

// ---------------- pre-round x and w_ih to fp16 ----------------
#define XF4 (TBH/4)                    // 8,388,608 float4 groups
#define WF4 ((size_t)2*G_*H_/4)        // 2,097,152
__global__ void round_all(const float* __restrict__ x, const float* __restrict__ wih) {
    const size_t stride = (size_t)gridDim.x * blockDim.x;
    for (size_t i = (size_t)blockIdx.x * blockDim.x + threadIdx.x; i < XF4 + WF4; i += stride) {
        float4 v; __half2* dst;
        if (i < XF4) {
            v = reinterpret_cast<const float4*>(x)[i];
            dst = reinterpret_cast<__half2*>(g_xh) + i * 2;
        } else {
            v = reinterpret_cast<const float4*>(wih)[i - XF4];
            dst = reinterpret_cast<__half2*>(g_wh) + (i - XF4) * 2;
        }
        dst[0] = __floats2half2_rn(v.x, v.y);
        dst[1] = __floats2half2_rn(v.z, v.w);
    }
}

// ============ Stage 1: xin[32768,4096] = A[32768,1024] @ W[4096,1024]^T (fp16) ============
// Tile 128x128, kc=64, cp.async double-buffered. 8 warps = 2(M) x 4(N), warp 64x32.
#define GA 9216                               // halves per buffer (128*72)
#define GX_SMEM (4*GA*2)                      // 73728 bytes
__global__ __launch_bounds__(256) void gemm_xin(int layer) {
    extern __shared__ __half smh[];
    __half* As = smh;                         // bufs @ 0, GA
    __half* Bs = smh + 2*GA;                  // bufs @ 0, GA

    const __half* A = (layer == 0) ? g_xh : g_s0h;
    const __half* W = g_wh + (size_t)layer * (size_t)G_ * H_;

    const int tid  = threadIdx.x;
    const int warp = tid >> 5;
    const int wm   = warp >> 2;
    const int wn   = warp & 3;
    const size_t m0 = (size_t)blockIdx.y * 128;
    const int    n0 = blockIdx.x * 128;

    const int r8 = tid >> 3, c8 = (tid & 7) << 3;    // 32 rows x 64 cols per pass
    const uint32_t sa = smem_u32(As), sb = smem_u32(Bs);

    wmma::fragment<wmma::accumulator,16,16,16,float> acc[4][2];
    #pragma unroll
    for (int mi = 0; mi < 4; mi++)
        #pragma unroll
        for (int ni = 0; ni < 2; ni++)
            wmma::fill_fragment(acc[mi][ni], 0.0f);

    // preload chunk 0 into buffer 0
    #pragma unroll
    for (int i = 0; i < 4; i++) {
        int rr = r8 + i*32;
        CP_ASYNC16(sa + (uint32_t)(rr*72 + c8)*2, &A[(m0 + rr)*1024 + c8]);
        CP_ASYNC16(sb + (uint32_t)(rr*72 + c8)*2, &W[(size_t)(n0 + rr)*1024 + c8]);
    }
    CP_COMMIT();

    for (int it = 0; it < 16; ++it) {
        const int buf = it & 1;
        if (it < 15) {
            const int kc = (it + 1) * 64;
            const uint32_t da = sa + (uint32_t)((buf^1)*GA)*2;
            const uint32_t db = sb + (uint32_t)((buf^1)*GA)*2;
            #pragma unroll
            for (int i = 0; i < 4; i++) {
                int rr = r8 + i*32;
                CP_ASYNC16(da + (uint32_t)(rr*72 + c8)*2, &A[(m0 + rr)*1024 + kc + c8]);
                CP_ASYNC16(db + (uint32_t)(rr*72 + c8)*2, &W[(size_t)(n0 + rr)*1024 + kc + c8]);
            }
            CP_COMMIT();
            CP_WAIT(1);
        } else {
            CP_WAIT(0);
        }
        __syncthreads();
        const __half* Ab = As + buf*GA;
        const __half* Bb = Bs + buf*GA;
        #pragma unroll
        for (int k16 = 0; k16 < 4; k16++) {
            wmma::fragment<wmma::matrix_a,16,16,16,__half,wmma::row_major> af[4];
            wmma::fragment<wmma::matrix_b,16,16,16,__half,wmma::col_major> bf[2];
            #pragma unroll
            for (int mi = 0; mi < 4; mi++)
                wmma::load_matrix_sync(af[mi], &Ab[(wm*64 + mi*16)*72 + k16*16], 72);
            #pragma unroll
            for (int ni = 0; ni < 2; ni++)
                wmma::load_matrix_sync(bf[ni], &Bb[(wn*32 + ni*16)*72 + k16*16], 72);
            #pragma unroll
            for (int mi = 0; mi < 4; mi++)
                #pragma unroll
                for (int ni = 0; ni < 2; ni++)
                    wmma::mma_sync(acc[mi][ni], af[mi], bf[ni], acc[mi][ni]);
        }
        __syncthreads();
    }
    #pragma unroll
    for (int mi = 0; mi < 4; mi++)
        #pragma unroll
        for (int ni = 0; ni < 2; ni++)
            wmma::store_matrix_sync(
                &g_xin[(m0 + wm*64 + mi*16)*(size_t)G_ + n0 + wn*32 + ni*16],
                acc[mi][ni], G_, wmma::mem_row_major);
}

// ============ Stage 2: persistent recurrence (fp16), 128 co-resident CTAs ============
// byte offsets:  Ws half 32x1032 @0 (66048B) | Hs half 2x(64x136) @66048 (34816B)
//                Ps float 8x32x36 @100864 (36864B) | Cs float 512 @137728 | Bsum 32 @139776
#define RB_WS   0
#define RB_HS   66048
#define RB_PS   100864
#define RB_CS   137728
#define RB_BS   139776
#define SMEM_BYTES 139904

__global__ __launch_bounds__(256) void lstm_rec(const float* __restrict__ whh,
                                                const float* __restrict__ bih,
                                                const float* __restrict__ bhh,
                                                float* __restrict__ out,
                                                int layer) {
    extern __shared__ char smc[];
    __half* Ws   = reinterpret_cast<__half*>(smc + RB_WS);
    __half* Hs   = reinterpret_cast<__half*>(smc + RB_HS);
    float*  Ps   = reinterpret_cast<float*>(smc + RB_PS);
    float*  Cs   = reinterpret_cast<float*>(smc + RB_CS);
    float*  Bsum = reinterpret_cast<float*>(smc + RB_BS);

    const int tid  = threadIdx.x;
    const int warp = tid >> 5;
    const int lane = tid & 31;
    const int wm   = warp & 1;            // batch half (32 rows)
    const int wk   = warp >> 1;           // K quarter within each 128-chunk
    const int j0   = blockIdx.x * 8;

    const float* whh_l = whh + (size_t)layer * (size_t)G_ * H_;
    const float* bih_l = bih + (size_t)layer * G_;
    const float* bhh_l = bhh + (size_t)layer * G_;
    float* hn_out = out + TBH + (size_t)layer * BH;
    float* cn_out = out + TBH + 2*(size_t)BH + (size_t)layer * BH;
    const uint32_t hs_b = smem_u32(Hs);

    // Stage w_hh rows (n = gate*8 + jj) as fp16.
    #pragma unroll 4
    for (int i = 0; i < 32; i++) {
        int idx = i*256 + tid;            // 8192 x float4
        int rr = idx >> 8;
        int cc = (idx & 255) << 2;
        int grow = (rr >> 3) * H_ + j0 + (rr & 7);
        float4 v = *reinterpret_cast<const float4*>(&whh_l[(size_t)grow * H_ + cc]);
        __half2* d = reinterpret_cast<__half2*>(&Ws[rr*1032 + cc]);
        d[0] = __floats2half2_rn(v.x, v.y);
        d[1] = __floats2half2_rn(v.z, v.w);
    }
    if (tid < 32) {
        int grow = (tid >> 3) * H_ + j0 + (tid & 7);
        Bsum[tid] = bih_l[grow] + bhh_l[grow];
    }
    Cs[tid] = 0.0f; Cs[tid + 256] = 0.0f;
    __syncthreads();

    const int b0 = tid >> 3, jj = tid & 7;
    const int b1 = (tid + 256) >> 3;

    for (int t = 0; t < T_; ++t) {
        const __half* hprev = g_h + (size_t)(t & 1) * BH;
        __half*       hnext = g_h + (size_t)((t + 1) & 1) * BH;

        float xr[8];
        {
            const float* xb = g_xin + (size_t)t * B_ * G_ + j0 + jj;
            const float* p0 = xb + (size_t)b0 * G_;
            const float* p1 = xb + (size_t)b1 * G_;
            xr[0]=p0[0]; xr[1]=p0[1024]; xr[2]=p0[2048]; xr[3]=p0[3072];
            xr[4]=p1[0]; xr[5]=p1[1024]; xr[6]=p1[2048]; xr[7]=p1[3072];
        }

        wmma::fragment<wmma::accumulator,16,16,16,float> acc[2][2];
        #pragma unroll
        for (int mi = 0; mi < 2; mi++)
            #pragma unroll
            for (int ni = 0; ni < 2; ni++)
                wmma::fill_fragment(acc[mi][ni], 0.0f);

        // prologue: async-load chunk 0 of h into Hs buf 0
        #pragma unroll
        for (int i = 0; i < 4; i++) {
            int idx = i*256 + tid;               // 1024 x 16B
            int rr = idx >> 4, cc = (idx & 15) << 3;
            CP_ASYNC16(hs_b + (uint32_t)(rr*136 + cc)*2, &hprev[(size_t)rr*H_ + cc]);
        }
        CP_COMMIT();

        for (int ch = 0; ch < 8; ch++) {
            const int buf = ch & 1;
            if (ch < 7) {
                const int kc = (ch + 1) * 128;
                const uint32_t dh = hs_b + (uint32_t)((buf^1)*8704)*2;
                #pragma unroll
                for (int i = 0; i < 4; i++) {
                    int idx = i*256 + tid;
                    int rr = idx >> 4, cc = (idx & 15) << 3;
                    CP_ASYNC16(dh + (uint32_t)(rr*136 + cc)*2, &hprev[(size_t)rr*H_ + kc + cc]);
                }
                CP_COMMIT();
                CP_WAIT(1);
            } else {
                CP_WAIT(0);
            }
            __syncthreads();
            const __half* Hb = Hs + buf*8704;
            #pragma unroll
            for (int k16 = 0; k16 < 2; k16++) {
                const int koff = wk*32 + k16*16;
                wmma::fragment<wmma::matrix_a,16,16,16,__half,wmma::row_major> af[2];
                wmma::fragment<wmma::matrix_b,16,16,16,__half,wmma::col_major> bf[2];
                wmma::load_matrix_sync(af[0], &Hb[(wm*32     )*136 + koff], 136);
                wmma::load_matrix_sync(af[1], &Hb[(wm*32 + 16)*136 + koff], 136);
                wmma::load_matrix_sync(bf[0], &Ws[          ch*128 + koff], 1032);
                wmma::load_matrix_sync(bf[1], &Ws[16*1032 + ch*128 + koff], 1032);
                #pragma unroll
                for (int mi = 0; mi < 2; mi++)
                    #pragma unroll
                    for (int ni = 0; ni < 2; ni++)
                        wmma::mma_sync(acc[mi][ni], af[mi], bf[ni], acc[mi][ni]);
            }
            __syncthreads();
        }

        #pragma unroll
        for (int mi = 0; mi < 2; mi++)
            #pragma unroll
            for (int ni = 0; ni < 2; ni++)
                wmma::store_matrix_sync(&Ps[warp*1152 + (mi*16)*36 + ni*16],
                                        acc[mi][ni], 36, wmma::mem_row_major);
        __syncthreads();

        #pragma unroll
        for (int h2 = 0; h2 < 2; h2++) {
            int e  = tid + h2*256;
            int b  = e >> 3;
            int wmb = b >> 5, br = b & 31;
            float s[4];
            #pragma unroll
            for (int g = 0; g < 4; g++) {
                int n = g*8 + jj;
                float a = Ps[(0*2+wmb)*1152 + br*36 + n]
                        + Ps[(1*2+wmb)*1152 + br*36 + n]
                        + Ps[(2*2+wmb)*1152 + br*36 + n]
                        + Ps[(3*2+wmb)*1152 + br*36 + n];
                s[g] = a + xr[h2*4 + g] + Bsum[n];
            }
            float si = 1.0f / (1.0f + __expf(-s[0]));
            float sf = 1.0f / (1.0f + __expf(-s[1]));
            float so = 1.0f / (1.0f + __expf(-s[3]));
            float cv = sf * Cs[e] + si * tanhf(s[2]);
            float hv = so * tanhf(cv);
            Cs[e] = cv;
            hnext[(size_t)b*H_ + j0 + jj] = __float2half_rn(hv);
            if (layer == 0)
                g_s0h[((size_t)t * B_ + b) * H_ + j0 + jj] = __float2half_rn(hv);
            else
                out[((size_t)t * B_ + b) * H_ + j0 + jj] = hv;
            if (t == T_ - 1) {
                hn_out[(size_t)b*H_ + j0 + jj] = hv;
                cn_out[(size_t)b*H_ + j0 + jj] = cv;
            }
        }
        __syncthreads();

        if (warp == 0) {
            if (lane == 0) {
                __threadfence();
                *reinterpret_cast<volatile unsigned*>(&g_flag[blockIdx.x]) = (unsigned)(t + 1);
            }
            const unsigned tgt = (unsigned)(t + 1);
            for (;;) {
                unsigned m0 = __ldcg(&g_flag[lane]);
                unsigned m1 = __ldcg(&g_flag[lane + 32]);
                unsigned m2 = __ldcg(&g_flag[lane + 64]);
                unsigned m3 = __ldcg(&g_flag[lane + 96]);
                unsigned mn = min(min(m0, m1), min(m2, m3));
                #pragma unroll
                for (int o = 16; o; o >>= 1)
                    mn = min(mn, __shfl_xor_sync(0xffffffffu, mn, o));
                if (mn >= tgt) break;
                __nanosleep(32);
            }
            __threadfence();
        }
        __syncthreads();
    }
}

// ---------------- launch ----------------
extern "C" void kernel_launch(void* const* d_in, const int* in_sizes, int n_in,
                              void* d_out, int out_size) {
    const float* x   = (const float*)d_in[0];
    const float* wih = (const float*)d_in[1];
    const float* whh = (const float*)d_in[2];
    const float* bih = (const float*)d_in[3];
    const float* bhh = (const float*)d_in[4];
    float* out = (float*)d_out;

    cudaFuncSetAttribute(lstm_rec, cudaFuncAttributeMaxDynamicSharedMemorySize, SMEM_BYTES);
    cudaFuncSetAttribute(gemm_xin, cudaFuncAttributeMaxDynamicSharedMemorySize, GX_SMEM);

    init_kernel<<<128, 256>>>();                                  // #1
    round_all<<<4096, 256>>>(x, wih);                             // #2
    gemm_xin<<<dim3(32, 256), 256, GX_SMEM>>>(0);                 // #3
    lstm_rec<<<NCTA, 256, SMEM_BYTES>>>(whh, bih, bhh, out, 0);   // #4 -> ncu slot 6
    init_kernel<<<128, 256>>>();
    gemm_xin<<<dim3(32, 256), 256, GX_SMEM>>>(1);
    lstm_rec<<<NCTA, 256, SMEM_BYTES>>>(whh, bih, bhh, out, 1);
}

// round 10
// speedup vs baseline: 2.3770x; 1.1999x over previous
#include <cuda_runtime.h>
#include <cuda_fp16.h>
#include <mma.h>
#include <cstdint>

using namespace nvcuda;

#define T_  512
#define B_  64
#define H_  1024
#define G_  4096
#define BH  (B_*H_)
#define TBH ((size_t)T_*B_*H_)
#define NCTA 128

// ---------------- device scratch (no allocations allowed) ----------------
__device__ float    g_xin[(size_t)T_*B_*G_];     // input projection (fp32, per layer)
__device__ __half   g_xh[TBH];                   // x rounded to fp16
__device__ __half   g_wh[(size_t)2*G_*H_];       // w_ih rounded to fp16
__device__ __half   g_s0h[TBH];                  // layer-0 seq (fp16, feeds layer-1 gemm)
__device__ __half   g_h[2*BH];                   // double-buffered h state (fp16)
__device__ unsigned g_flag[NCTA];                // per-CTA step flags

__device__ __forceinline__ uint32_t smem_u32(const void* p) {
    uint32_t a;
    asm("{ .reg .u64 t; cvta.to.shared.u64 t, %1; cvt.u32.u64 %0, t; }" : "=r"(a) : "l"(p));
    return a;
}
__device__ __forceinline__ unsigned ld_acq(const unsigned* p) {
    unsigned v;
    asm volatile("ld.acquire.gpu.global.u32 %0, [%1];" : "=r"(v) : "l"(p) : "memory");
    return v;
}
__device__ __forceinline__ void st_rel(unsigned* p, unsigned v) {
    asm volatile("st.release.gpu.global.u32 [%0], %1;" :: "l"(p), "r"(v) : "memory");
}
#define CP_ASYNC16(dst_u32, src_ptr) \
    asm volatile("cp.async.cg.shared.global [%0], [%1], 16;" :: "r"(dst_u32), "l"(src_ptr))
#define CP_COMMIT() asm volatile("cp.async.commit_group;" ::: "memory")
#define CP_WAIT(n)  asm volatile("cp.async.wait_group %0;" :: "n"(n) : "memory")

// ---------------- init: zero h buffers + flags ----------------
__global__ void init_kernel() {
    int i = blockIdx.x * blockDim.x + threadIdx.x;   // 32768 threads
    float* hz = reinterpret_cast<float*>(g_h);       // 2*BH halves = 65536 floats
    hz[i] = 0.0f; hz[i + 32768] = 0.0f;
    if (i < NCTA) g_flag[i] = 0u;
}

// ---------------- pre-round x and w_ih to fp16 ----------------
#define XF4 (TBH/4)
#define WF4 ((size_t)2*G_*H_/4)
__global__ void round_all(const float* __restrict__ x, const float* __restrict__ wih) {
    const size_t stride = (size_t)gridDim.x * blockDim.x;
    for (size_t i = (size_t)blockIdx.x * blockDim.x + threadIdx.x; i < XF4 + WF4; i += stride) {
        float4 v; __half2* dst;
        if (i < XF4) {
            v = reinterpret_cast<const float4*>(x)[i];
            dst = reinterpret_cast<__half2*>(g_xh) + i * 2;
        } else {
            v = reinterpret_cast<const float4*>(wih)[i - XF4];
            dst = reinterpret_cast<__half2*>(g_wh) + (i - XF4) * 2;
        }
        dst[0] = __floats2half2_rn(v.x, v.y);
        dst[1] = __floats2half2_rn(v.z, v.w);
    }
}

// ============ Stage 1: xin[32768,4096] = A[32768,1024] @ W[4096,1024]^T (fp16) ============
#define GA 9216
#define GX_SMEM (4*GA*2)
__global__ __launch_bounds__(256) void gemm_xin(int layer) {
    extern __shared__ __half smh[];
    __half* As = smh;
    __half* Bs = smh + 2*GA;

    const __half* A = (layer == 0) ? g_xh : g_s0h;
    const __half* W = g_wh + (size_t)layer * (size_t)G_ * H_;

    const int tid  = threadIdx.x;
    const int warp = tid >> 5;
    const int wm   = warp >> 2;
    const int wn   = warp & 3;
    const size_t m0 = (size_t)blockIdx.y * 128;
    const int    n0 = blockIdx.x * 128;

    const int r8 = tid >> 3, c8 = (tid & 7) << 3;
    const uint32_t sa = smem_u32(As), sb = smem_u32(Bs);

    wmma::fragment<wmma::accumulator,16,16,16,float> acc[4][2];
    #pragma unroll
    for (int mi = 0; mi < 4; mi++)
        #pragma unroll
        for (int ni = 0; ni < 2; ni++)
            wmma::fill_fragment(acc[mi][ni], 0.0f);

    #pragma unroll
    for (int i = 0; i < 4; i++) {
        int rr = r8 + i*32;
        CP_ASYNC16(sa + (uint32_t)(rr*72 + c8)*2, &A[(m0 + rr)*1024 + c8]);
        CP_ASYNC16(sb + (uint32_t)(rr*72 + c8)*2, &W[(size_t)(n0 + rr)*1024 + c8]);
    }
    CP_COMMIT();

    for (int it = 0; it < 16; ++it) {
        const int buf = it & 1;
        if (it < 15) {
            const int kc = (it + 1) * 64;
            const uint32_t da = sa + (uint32_t)((buf^1)*GA)*2;
            const uint32_t db = sb + (uint32_t)((buf^1)*GA)*2;
            #pragma unroll
            for (int i = 0; i < 4; i++) {
                int rr = r8 + i*32;
                CP_ASYNC16(da + (uint32_t)(rr*72 + c8)*2, &A[(m0 + rr)*1024 + kc + c8]);
                CP_ASYNC16(db + (uint32_t)(rr*72 + c8)*2, &W[(size_t)(n0 + rr)*1024 + kc + c8]);
            }
            CP_COMMIT();
            CP_WAIT(1);
        } else {
            CP_WAIT(0);
        }
        __syncthreads();
        const __half* Ab = As + buf*GA;
        const __half* Bb = Bs + buf*GA;
        #pragma unroll
        for (int k16 = 0; k16 < 4; k16++) {
            wmma::fragment<wmma::matrix_a,16,16,16,__half,wmma::row_major> af[4];
            wmma::fragment<wmma::matrix_b,16,16,16,__half,wmma::col_major> bf[2];
            #pragma unroll
            for (int mi = 0; mi < 4; mi++)
                wmma::load_matrix_sync(af[mi], &Ab[(wm*64 + mi*16)*72 + k16*16], 72);
            #pragma unroll
            for (int ni = 0; ni < 2; ni++)
                wmma::load_matrix_sync(bf[ni], &Bb[(wn*32 + ni*16)*72 + k16*16], 72);
            #pragma unroll
            for (int mi = 0; mi < 4; mi++)
                #pragma unroll
                for (int ni = 0; ni < 2; ni++)
                    wmma::mma_sync(acc[mi][ni], af[mi], bf[ni], acc[mi][ni]);
        }
        __syncthreads();
    }
    #pragma unroll
    for (int mi = 0; mi < 4; mi++)
        #pragma unroll
        for (int ni = 0; ni < 2; ni++)
            wmma::store_matrix_sync(
                &g_xin[(m0 + wm*64 + mi*16)*(size_t)G_ + n0 + wn*32 + ni*16],
                acc[mi][ni], G_, wmma::mem_row_major);
}

// ============ Stage 2: persistent recurrence (fp16), dataflow flags ============
// byte offsets: Ws half 32x1032 @0 (66048B) | Hs half 2x(64x264) @66048 (67584B)
//               Ps float 8x32x36 @133632 (36864B) | Cs 512 @170496 | Bsum 32 @172544
#define RB_WS   0
#define RB_HS   66048
#define RB_PS   133632
#define RB_CS   170496
#define RB_BS   172544
#define SMEM_BYTES 172672
#define HS_BUF  16896                      // halves per Hs buffer (64*264)

__global__ __launch_bounds__(256) void lstm_rec(const float* __restrict__ whh,
                                                const float* __restrict__ bih,
                                                const float* __restrict__ bhh,
                                                float* __restrict__ out,
                                                int layer) {
    extern __shared__ char smc[];
    __half* Ws   = reinterpret_cast<__half*>(smc + RB_WS);
    __half* Hs   = reinterpret_cast<__half*>(smc + RB_HS);
    float*  Ps   = reinterpret_cast<float*>(smc + RB_PS);
    float*  Cs   = reinterpret_cast<float*>(smc + RB_CS);
    float*  Bsum = reinterpret_cast<float*>(smc + RB_BS);

    const int tid  = threadIdx.x;
    const int warp = tid >> 5;
    const int wm   = warp & 1;            // batch half (32 rows)
    const int wk   = warp >> 1;           // K quarter within each 256-chunk
    const int j0   = blockIdx.x * 8;

    const float* whh_l = whh + (size_t)layer * (size_t)G_ * H_;
    const float* bih_l = bih + (size_t)layer * G_;
    const float* bhh_l = bhh + (size_t)layer * G_;
    float* hn_out = out + TBH + (size_t)layer * BH;
    float* cn_out = out + TBH + 2*(size_t)BH + (size_t)layer * BH;
    const uint32_t hs_b = smem_u32(Hs);

    // this thread's column-octet within any chunk -> exactly one producer flag
    const int rr_c = tid >> 5;                  // base row pattern helper
    const int cc8  = (tid & 31) << 3;           // col offset within chunk (0..248)
    const int fidx = (tid & 31);                // flag lane within chunk group

    // Stage w_hh rows (n = gate*8 + jj) as fp16.
    #pragma unroll 4
    for (int i = 0; i < 32; i++) {
        int idx = i*256 + tid;
        int rr = idx >> 8;
        int cc = (idx & 255) << 2;
        int grow = (rr >> 3) * H_ + j0 + (rr & 7);
        float4 v = *reinterpret_cast<const float4*>(&whh_l[(size_t)grow * H_ + cc]);
        __half2* d = reinterpret_cast<__half2*>(&Ws[rr*1032 + cc]);
        d[0] = __floats2half2_rn(v.x, v.y);
        d[1] = __floats2half2_rn(v.z, v.w);
    }
    if (tid < 32) {
        int grow = (tid >> 3) * H_ + j0 + (tid & 7);
        Bsum[tid] = bih_l[grow] + bhh_l[grow];
    }
    Cs[tid] = 0.0f; Cs[tid + 256] = 0.0f;
    __syncthreads();

    const int b0 = tid >> 3, jj = tid & 7;
    const int b1 = (tid + 256) >> 3;

    for (int t = 0; t < T_; ++t) {
        const __half* hprev = g_h + (size_t)(t & 1) * BH;
        __half*       hnext = g_h + (size_t)((t + 1) & 1) * BH;
        const unsigned tgt = (unsigned)t;

        // xin prefetch (independent of h)
        float xr[8];
        {
            const float* xb = g_xin + (size_t)t * B_ * G_ + j0 + jj;
            const float* p0 = xb + (size_t)b0 * G_;
            const float* p1 = xb + (size_t)b1 * G_;
            xr[0]=p0[0]; xr[1]=p0[1024]; xr[2]=p0[2048]; xr[3]=p0[3072];
            xr[4]=p1[0]; xr[5]=p1[1024]; xr[6]=p1[2048]; xr[7]=p1[3072];
        }

        wmma::fragment<wmma::accumulator,16,16,16,float> acc[2][2];
        #pragma unroll
        for (int mi = 0; mi < 2; mi++)
            #pragma unroll
            for (int ni = 0; ni < 2; ni++)
                wmma::fill_fragment(acc[mi][ni], 0.0f);

        // prologue: dataflow wait on chunk 0's producer, then async-load chunk 0
        if (ld_acq(&g_flag[fidx]) < tgt)
            while (ld_acq(&g_flag[fidx]) < tgt) __nanosleep(20);
        #pragma unroll
        for (int i = 0; i < 8; i++) {
            int rr = rr_c + i*8;                        // 8 rows per thread
            CP_ASYNC16(hs_b + (uint32_t)(rr*264 + cc8)*2, &hprev[(size_t)rr*H_ + cc8]);
        }
        CP_COMMIT();

        for (int ch = 0; ch < 4; ch++) {
            const int buf = ch & 1;
            if (ch < 3) {
                const int kc = (ch + 1) * 256;
                const unsigned* fl = &g_flag[32*(ch+1) + fidx];
                if (ld_acq(fl) < tgt)
                    while (ld_acq(fl) < tgt) __nanosleep(20);
                const uint32_t dh = hs_b + (uint32_t)((buf^1)*HS_BUF)*2;
                #pragma unroll
                for (int i = 0; i < 8; i++) {
                    int rr = rr_c + i*8;
                    CP_ASYNC16(dh + (uint32_t)(rr*264 + cc8)*2, &hprev[(size_t)rr*H_ + kc + cc8]);
                }
                CP_COMMIT();
                CP_WAIT(1);
            } else {
                CP_WAIT(0);
            }
            __syncthreads();
            const __half* Hb = Hs + buf*HS_BUF;
            #pragma unroll
            for (int k16 = 0; k16 < 4; k16++) {
                const int koff = wk*64 + k16*16;
                wmma::fragment<wmma::matrix_a,16,16,16,__half,wmma::row_major> af[2];
                wmma::fragment<wmma::matrix_b,16,16,16,__half,wmma::col_major> bf[2];
                wmma::load_matrix_sync(af[0], &Hb[(wm*32     )*264 + koff], 264);
                wmma::load_matrix_sync(af[1], &Hb[(wm*32 + 16)*264 + koff], 264);
                wmma::load_matrix_sync(bf[0], &Ws[          ch*256 + koff], 1032);
                wmma::load_matrix_sync(bf[1], &Ws[16*1032 + ch*256 + koff], 1032);
                #pragma unroll
                for (int mi = 0; mi < 2; mi++)
                    #pragma unroll
                    for (int ni = 0; ni < 2; ni++)
                        wmma::mma_sync(acc[mi][ni], af[mi], bf[ni], acc[mi][ni]);
            }
            __syncthreads();
        }

        #pragma unroll
        for (int mi = 0; mi < 2; mi++)
            #pragma unroll
            for (int ni = 0; ni < 2; ni++)
                wmma::store_matrix_sync(&Ps[warp*1152 + (mi*16)*36 + ni*16],
                                        acc[mi][ni], 36, wmma::mem_row_major);
        __syncthreads();

        #pragma unroll
        for (int h2 = 0; h2 < 2; h2++) {
            int e  = tid + h2*256;
            int b  = e >> 3;
            int wmb = b >> 5, br = b & 31;
            float s[4];
            #pragma unroll
            for (int g = 0; g < 4; g++) {
                int n = g*8 + jj;
                float a = Ps[(0*2+wmb)*1152 + br*36 + n]
                        + Ps[(1*2+wmb)*1152 + br*36 + n]
                        + Ps[(2*2+wmb)*1152 + br*36 + n]
                        + Ps[(3*2+wmb)*1152 + br*36 + n];
                s[g] = a + xr[h2*4 + g] + Bsum[n];
            }
            float si = 1.0f / (1.0f + __expf(-s[0]));
            float sf = 1.0f / (1.0f + __expf(-s[1]));
            float so = 1.0f / (1.0f + __expf(-s[3]));
            float cv = sf * Cs[e] + si * tanhf(s[2]);
            float hv = so * tanhf(cv);
            Cs[e] = cv;
            hnext[(size_t)b*H_ + j0 + jj] = __float2half_rn(hv);
            if (layer == 0)
                g_s0h[((size_t)t * B_ + b) * H_ + j0 + jj] = __float2half_rn(hv);
            else
                out[((size_t)t * B_ + b) * H_ + j0 + jj] = hv;
            if (t == T_ - 1) {
                hn_out[(size_t)b*H_ + j0 + jj] = hv;
                cn_out[(size_t)b*H_ + j0 + jj] = cv;
            }
        }
        // publish: all threads fence, sync, one release-store
        __threadfence();
        __syncthreads();
        if (tid == 0) st_rel(&g_flag[blockIdx.x], (unsigned)(t + 1));
    }
}

// ---------------- launch ----------------
extern "C" void kernel_launch(void* const* d_in, const int* in_sizes, int n_in,
                              void* d_out, int out_size) {
    const float* x   = (const float*)d_in[0];
    const float* wih = (const float*)d_in[1];
    const float* whh = (const float*)d_in[2];
    const float* bih = (const float*)d_in[3];
    const float* bhh = (const float*)d_in[4];
    float* out = (float*)d_out;

    cudaFuncSetAttribute(lstm_rec, cudaFuncAttributeMaxDynamicSharedMemorySize, SMEM_BYTES);
    cudaFuncSetAttribute(gemm_xin, cudaFuncAttributeMaxDynamicSharedMemorySize, GX_SMEM);

    init_kernel<<<128, 256>>>();                                  // #1
    round_all<<<4096, 256>>>(x, wih);                             // #2
    gemm_xin<<<dim3(32, 256), 256, GX_SMEM>>>(0);                 // #3
    lstm_rec<<<NCTA, 256, SMEM_BYTES>>>(whh, bih, bhh, out, 0);   // #4 -> ncu slot 6
    init_kernel<<<128, 256>>>();
    gemm_xin<<<dim3(32, 256), 256, GX_SMEM>>>(1);
    lstm_rec<<<NCTA, 256, SMEM_BYTES>>>(whh, bih, bhh, out, 1);
}